// round 12
// baseline (speedup 1.0000x reference)
#include <cuda_runtime.h>
#include <cuda_bf16.h>
#include <cuda_fp16.h>
#include <math.h>
#include <stdint.h>

#define T_DIM 8192
#define OBS 512
#define HID 2048
#define NOBJ 8

#define NCHUNK 128
#define LC (T_DIM / NCHUNK)   // 64

// ---------------------------------------------------------------------------
// Scratch (device globals; no allocation allowed).
// g_h16[0]=x_state, g_h16[1]=B, g_h16[2]=C (fp16); g_buf[3]=delta_raw (fp32);
// g_y16 = y (fp16, scan output)
__device__ float g_buf[4][(size_t)T_DIM * HID];
__device__ __half g_h16[3][(size_t)T_DIM * HID];
__device__ __half g_y16[(size_t)T_DIM * HID];
__device__ float g_aggA[NCHUNK * HID];
__device__ float g_aggB[NCHUNK * HID];
__device__ float g_hinit[NCHUNK * HID];
// bf16 hi/lo split operands
__device__ __nv_bfloat16 g_xhi[(size_t)T_DIM * OBS];
__device__ __nv_bfloat16 g_xlo[(size_t)T_DIM * OBS];
__device__ __nv_bfloat16 g_whi[4ull * HID * OBS];
__device__ __nv_bfloat16 g_wlo[4ull * HID * OBS];

// ---------------------------------------------------------------------------
__device__ __forceinline__ uint32_t smem_to_u32(const void* p) {
    uint32_t a;
    asm("{ .reg .u64 t; cvta.to.shared.u64 t, %1; cvt.u32.u64 %0, t; }" : "=r"(a) : "l"(p));
    return a;
}
__device__ __forceinline__ void cp16(uint32_t dst, const void* src) {
    asm volatile("cp.async.cg.shared.global [%0], [%1], 16;" :: "r"(dst), "l"(src));
}
__device__ __forceinline__ void cp_commit() { asm volatile("cp.async.commit_group;"); }
__device__ __forceinline__ void ldsm4(uint32_t* r, uint32_t addr) {
    asm volatile("ldmatrix.sync.aligned.m8n8.x4.shared.b16 {%0,%1,%2,%3}, [%4];"
                 : "=r"(r[0]), "=r"(r[1]), "=r"(r[2]), "=r"(r[3]) : "r"(addr));
}
__device__ __forceinline__ void mma16816(float* c, const uint32_t* a, uint32_t b0, uint32_t b1) {
    asm volatile(
        "mma.sync.aligned.m16n8k16.row.col.f32.bf16.bf16.f32 "
        "{%0,%1,%2,%3}, {%4,%5,%6,%7}, {%8,%9}, {%0,%1,%2,%3};"
        : "+f"(c[0]), "+f"(c[1]), "+f"(c[2]), "+f"(c[3])
        : "r"(a[0]), "r"(a[1]), "r"(a[2]), "r"(a[3]), "r"(b0), "r"(b1));
}
__device__ __forceinline__ uint32_t pack_bf16x2(float a, float b) {
    __nv_bfloat162 p = __floats2bfloat162_rn(a, b);
    return *(uint32_t*)&p;
}

// ---------------------------------------------------------------------------
// fp32 -> bf16 hi/lo conversion (vectorized)
// ---------------------------------------------------------------------------
__global__ void convert_x_kernel(const float* __restrict__ x) {
    size_t i = ((size_t)blockIdx.x * blockDim.x + threadIdx.x) * 4;
    float4 v = *(const float4*)(x + i);
    __nv_bfloat16 h0 = __float2bfloat16(v.x), h1 = __float2bfloat16(v.y);
    __nv_bfloat16 h2 = __float2bfloat16(v.z), h3 = __float2bfloat16(v.w);
    uint2 hp;
    hp.x = pack_bf16x2(__bfloat162float(h0), __bfloat162float(h1));
    hp.y = pack_bf16x2(__bfloat162float(h2), __bfloat162float(h3));
    *(uint2*)(g_xhi + i) = hp;
    uint2 lp;
    lp.x = pack_bf16x2(v.x - __bfloat162float(h0), v.y - __bfloat162float(h1));
    lp.y = pack_bf16x2(v.z - __bfloat162float(h2), v.w - __bfloat162float(h3));
    *(uint2*)(g_xlo + i) = lp;
}
__global__ void convert_w_kernel(const float* __restrict__ w0, const float* __restrict__ w1,
                                 const float* __restrict__ w2, const float* __restrict__ w3) {
    int z = blockIdx.y;
    const float* __restrict__ W = (z == 0) ? w0 : (z == 1) ? w1 : (z == 2) ? w2 : w3;
    size_t i = ((size_t)blockIdx.x * blockDim.x + threadIdx.x) * 4;
    float4 v = *(const float4*)(W + i);
    size_t o = (size_t)z * HID * OBS + i;
    __nv_bfloat16 h0 = __float2bfloat16(v.x), h1 = __float2bfloat16(v.y);
    __nv_bfloat16 h2 = __float2bfloat16(v.z), h3 = __float2bfloat16(v.w);
    uint2 hp;
    hp.x = pack_bf16x2(__bfloat162float(h0), __bfloat162float(h1));
    hp.y = pack_bf16x2(__bfloat162float(h2), __bfloat162float(h3));
    *(uint2*)(g_whi + o) = hp;
    uint2 lp;
    lp.x = pack_bf16x2(v.x - __bfloat162float(h0), v.y - __bfloat162float(h1));
    lp.y = pack_bf16x2(v.z - __bfloat162float(h2), v.w - __bfloat162float(h3));
    *(uint2*)(g_wlo + o) = lp;
}

// ---------------------------------------------------------------------------
// HMMA GEMM (proven ~122us/GEMM): G[z] = X . W_z^T, bf16 3-term hi/lo.
// BM=128, BN=128, BK=32. 4 warps 2x2, warp tile 64x64. 128 thr, 2 CTAs/SM.
// Epilogue: z<3 stores fp16 (x_state,B,C); z==3 stores fp32 delta_raw.
// ---------------------------------------------------------------------------
#define GBM 128
#define GBN 128
#define GBK 32
#define NS (OBS / GBK)           // 16
#define ROWB 80
#define A_BYTES (GBM * ROWB)     // 10240
#define B_BYTES (GBN * ROWB)     // 10240
#define STAGE_BYTES (2 * A_BYTES + 2 * B_BYTES)   // 40960
#define GEMM_SMEM (2 * STAGE_BYTES)               // 81920

__global__ __launch_bounds__(128, 2)
void gemm_hmma_kernel() {
    extern __shared__ char smem[];
    const uint32_t sbase = smem_to_u32(smem);
    const int tid = threadIdx.x;
    const int wid = tid >> 5;
    const int lane = tid & 31;
    const int wm = wid >> 1;         // 0..1 -> m offset *64
    const int wn = wid & 1;          // 0..1 -> n offset *64

    const int z = blockIdx.z;
    const int n0 = blockIdx.x * GBN;
    const int m0 = blockIdx.y * GBM;
    const __nv_bfloat16* __restrict__ whi = g_whi + (size_t)z * HID * OBS;
    const __nv_bfloat16* __restrict__ wlo = g_wlo + (size_t)z * HID * OBS;

    float acc[4][8][4];   // [mi][n8-frag][frag]
#pragma unroll
    for (int i = 0; i < 4; i++)
#pragma unroll
        for (int j = 0; j < 8; j++)
#pragma unroll
            for (int k = 0; k < 4; k++) acc[i][j][k] = 0.f;

    auto load_stage = [&](int s, int bi) {
        const int k0 = s * GBK;
        const uint32_t st = sbase + bi * STAGE_BYTES;
#pragma unroll
        for (int i = 0; i < 4; i++) {
            int idx = tid + 128 * i;          // 0..511
            int row = idx >> 2, c = idx & 3;
            size_t gsrc = (size_t)(m0 + row) * OBS + k0 + c * 8;
            uint32_t dst = st + row * ROWB + c * 16;
            cp16(dst,           g_xhi + gsrc);
            cp16(dst + A_BYTES, g_xlo + gsrc);
        }
#pragma unroll
        for (int i = 0; i < 4; i++) {
            int idx = tid + 128 * i;
            int row = idx >> 2, c = idx & 3;
            size_t gsrc = (size_t)(n0 + row) * OBS + k0 + c * 8;
            uint32_t dst = st + 2 * A_BYTES + row * ROWB + c * 16;
            cp16(dst,           whi + gsrc);
            cp16(dst + B_BYTES, wlo + gsrc);
        }
        cp_commit();
    };

    load_stage(0, 0);

    for (int s = 0; s < NS; s++) {
        if (s + 1 < NS) {
            load_stage(s + 1, (s + 1) & 1);
            asm volatile("cp.async.wait_group 1;" ::: "memory");
        } else {
            asm volatile("cp.async.wait_group 0;" ::: "memory");
        }
        __syncthreads();

        const uint32_t ab = sbase + (s & 1) * STAGE_BYTES;   // A hi
        const uint32_t bb = ab + 2 * A_BYTES;                // B hi

#pragma unroll
        for (int ks = 0; ks < 2; ks++) {
            uint32_t ahi[4][4], alo[4][4];
#pragma unroll
            for (int mi = 0; mi < 4; mi++) {
                uint32_t addr = ab + (wm * 64 + mi * 16 + (lane & 15)) * ROWB
                              + ks * 32 + (lane >> 4) * 16;
                ldsm4(ahi[mi], addr);
                ldsm4(alo[mi], addr + A_BYTES);
            }
            uint32_t bhi[4][4], blo[4][4];
#pragma unroll
            for (int np = 0; np < 4; np++) {
                uint32_t addr = bb + (wn * 64 + np * 16 + (lane >> 4) * 8 + (lane & 7)) * ROWB
                              + ks * 32 + ((lane >> 3) & 1) * 16;
                ldsm4(bhi[np], addr);
                ldsm4(blo[np], addr + B_BYTES);
            }
#pragma unroll
            for (int mi = 0; mi < 4; mi++)
#pragma unroll
                for (int np = 0; np < 4; np++) {
                    mma16816(acc[mi][np * 2],     ahi[mi], bhi[np][0], bhi[np][1]);
                    mma16816(acc[mi][np * 2 + 1], ahi[mi], bhi[np][2], bhi[np][3]);
                }
#pragma unroll
            for (int mi = 0; mi < 4; mi++)
#pragma unroll
                for (int np = 0; np < 4; np++) {
                    mma16816(acc[mi][np * 2],     ahi[mi], blo[np][0], blo[np][1]);
                    mma16816(acc[mi][np * 2 + 1], ahi[mi], blo[np][2], blo[np][3]);
                }
#pragma unroll
            for (int mi = 0; mi < 4; mi++)
#pragma unroll
                for (int np = 0; np < 4; np++) {
                    mma16816(acc[mi][np * 2],     alo[mi], bhi[np][0], bhi[np][1]);
                    mma16816(acc[mi][np * 2 + 1], alo[mi], bhi[np][2], bhi[np][3]);
                }
        }
        __syncthreads();
    }

    // Epilogue: z<3 -> fp16; z==3 (delta_raw) -> fp32
    if (z == 3) {
        float* __restrict__ G = g_buf[3];
#pragma unroll
        for (int mi = 0; mi < 4; mi++) {
            int row = m0 + wm * 64 + mi * 16 + (lane >> 2);
#pragma unroll
            for (int ni = 0; ni < 8; ni++) {
                int col = n0 + wn * 64 + ni * 8 + (lane & 3) * 2;
                *(float2*)(G + (size_t)row * HID + col) =
                    make_float2(acc[mi][ni][0], acc[mi][ni][1]);
                *(float2*)(G + (size_t)(row + 8) * HID + col) =
                    make_float2(acc[mi][ni][2], acc[mi][ni][3]);
            }
        }
    } else {
        __half* __restrict__ H = g_h16[z];
#pragma unroll
        for (int mi = 0; mi < 4; mi++) {
            int row = m0 + wm * 64 + mi * 16 + (lane >> 2);
#pragma unroll
            for (int ni = 0; ni < 8; ni++) {
                int col = n0 + wn * 64 + ni * 8 + (lane & 3) * 2;
                *(__half2*)(H + (size_t)row * HID + col) =
                    __floats2half2_rn(acc[mi][ni][0], acc[mi][ni][1]);
                *(__half2*)(H + (size_t)(row + 8) * HID + col) =
                    __floats2half2_rn(acc[mi][ni][2], acc[mi][ni][3]);
            }
        }
    }
}

// ---------------------------------------------------------------------------
// Scan pass 1: per-chunk aggregates only. 2 channels/thread (float2/half2).
// ---------------------------------------------------------------------------
__global__ void scan_chunk_kernel(const float* __restrict__ A_log) {
    int h = (blockIdx.x * blockDim.x + threadIdx.x) * 2;
    int c = blockIdx.y;
    float2 Al = *(const float2*)(A_log + h);
    float A0 = -expf(Al.x), A1 = -expf(Al.y);
    size_t base = (size_t)(c * LC) * HID + h;
    float ap0 = 1.f, ap1 = 1.f, bb0 = 0.f, bb1 = 0.f;
#pragma unroll 4
    for (int i = 0; i < LC; i++) {
        float2 dr = *(const float2*)(g_buf[3] + base);
        float2 xs = __half22float2(*(const __half2*)(g_h16[0] + base));
        float2 Bv = __half22float2(*(const __half2*)(g_h16[1] + base));
        float a0 = expf(A0 / (1.f + __expf(-dr.x)));
        float a1 = expf(A1 / (1.f + __expf(-dr.y)));
        ap0 *= a0; ap1 *= a1;
        bb0 = a0 * bb0 + Bv.x * xs.x;
        bb1 = a1 * bb1 + Bv.y * xs.y;
        base += HID;
    }
    *(float2*)(g_aggA + c * HID + h) = make_float2(ap0, ap1);
    *(float2*)(g_aggB + c * HID + h) = make_float2(bb0, bb1);
}

// ---------------------------------------------------------------------------
// Scan pass 2: warp-parallel scan of NCHUNK aggregates per channel.
// ---------------------------------------------------------------------------
__global__ void scan_agg_kernel() {
    int warp = threadIdx.x >> 5;
    int lane = threadIdx.x & 31;
    int h = blockIdx.x * 8 + warp;

    float a_loc[4], b_loc[4];
    float ca = 1.f, cb = 0.f;
    int cbase = lane * 4;
#pragma unroll
    for (int j = 0; j < 4; j++) {
        float a = g_aggA[(cbase + j) * HID + h];
        float b = g_aggB[(cbase + j) * HID + h];
        a_loc[j] = a; b_loc[j] = b;
        cb = a * cb + b;
        ca *= a;
    }
    float ia = ca, ib = cb;
#pragma unroll
    for (int off = 1; off < 32; off <<= 1) {
        float pa = __shfl_up_sync(0xFFFFFFFFu, ia, off);
        float pb = __shfl_up_sync(0xFFFFFFFFu, ib, off);
        if (lane >= off) {
            ib = ia * pb + ib;
            ia = ia * pa;
        }
    }
    float eb = __shfl_up_sync(0xFFFFFFFFu, ib, 1);
    if (lane == 0) eb = 0.f;
    float hcur = eb;
#pragma unroll
    for (int j = 0; j < 4; j++) {
        g_hinit[(cbase + j) * HID + h] = hcur;
        hcur = a_loc[j] * hcur + b_loc[j];
    }
}

// ---------------------------------------------------------------------------
// Scan pass 3: apply within chunk; y = C*h stored fp16. 2 channels/thread.
// ---------------------------------------------------------------------------
__global__ void scan_apply_kernel(const float* __restrict__ A_log) {
    int h = (blockIdx.x * blockDim.x + threadIdx.x) * 2;
    int c = blockIdx.y;
    float2 Al = *(const float2*)(A_log + h);
    float A0 = -expf(Al.x), A1 = -expf(Al.y);
    size_t base = (size_t)(c * LC) * HID + h;
    float2 hsv = *(const float2*)(g_hinit + c * HID + h);
    float hs0 = hsv.x, hs1 = hsv.y;
#pragma unroll 4
    for (int i = 0; i < LC; i++) {
        float2 dr = *(const float2*)(g_buf[3] + base);
        float2 xs = __half22float2(*(const __half2*)(g_h16[0] + base));
        float2 Bv = __half22float2(*(const __half2*)(g_h16[1] + base));
        float2 Cv = __half22float2(*(const __half2*)(g_h16[2] + base));
        float a0 = expf(A0 / (1.f + __expf(-dr.x)));
        float a1 = expf(A1 / (1.f + __expf(-dr.y)));
        hs0 = a0 * hs0 + Bv.x * xs.x;
        hs1 = a1 * hs1 + Bv.y * xs.y;
        *(__half2*)(g_y16 + base) = __floats2half2_rn(Cv.x * hs0, Cv.y * hs1);
        base += HID;
    }
}

// ---------------------------------------------------------------------------
// Output projection: warp per timestep; y read as half2.
// ---------------------------------------------------------------------------
__global__ void out_kernel(const float* __restrict__ x,
                           const float* __restrict__ W_out,
                           const float* __restrict__ b_out,
                           const float* __restrict__ W_skip,
                           float* __restrict__ out) {
    int warp = threadIdx.x >> 5;
    int lane = threadIdx.x & 31;
    int t = blockIdx.x * (blockDim.x >> 5) + warp;
    if (t >= T_DIM) return;

    float acc[NOBJ];
#pragma unroll
    for (int n = 0; n < NOBJ; n++) acc[n] = 0.f;

    const __half* yrow = g_y16 + (size_t)t * HID;
    for (int h = lane * 2; h < HID; h += 64) {
        float2 yv = __half22float2(*(const __half2*)(yrow + h));
#pragma unroll
        for (int n = 0; n < NOBJ; n++)
            acc[n] += yv.x * W_out[n * HID + h] + yv.y * W_out[n * HID + h + 1];
    }
    const float* xrow = x + (size_t)t * OBS;
    for (int o = lane; o < OBS; o += 32) {
        float xv = xrow[o];
#pragma unroll
        for (int n = 0; n < NOBJ; n++) acc[n] += xv * W_skip[n * OBS + o];
    }
#pragma unroll
    for (int n = 0; n < NOBJ; n++) {
#pragma unroll
        for (int off = 16; off > 0; off >>= 1)
            acc[n] += __shfl_down_sync(0xFFFFFFFFu, acc[n], off);
    }
    if (lane == 0) {
#pragma unroll
        for (int n = 0; n < NOBJ; n++)
            out[(size_t)t * NOBJ + n] = acc[n] + b_out[n];
    }
}

// ---------------------------------------------------------------------------
extern "C" void kernel_launch(void* const* d_in, const int* in_sizes, int n_in,
                              void* d_out, int out_size) {
    const float* x       = (const float*)d_in[0];
    const float* W_in    = (const float*)d_in[1];
    const float* W_B     = (const float*)d_in[2];
    const float* W_C     = (const float*)d_in[3];
    const float* W_delta = (const float*)d_in[4];
    const float* A_log   = (const float*)d_in[5];
    const float* W_out   = (const float*)d_in[6];
    const float* b_out   = (const float*)d_in[7];
    const float* W_skip  = (const float*)d_in[8];
    float* out = (float*)d_out;

    cudaFuncSetAttribute(gemm_hmma_kernel, cudaFuncAttributeMaxDynamicSharedMemorySize, GEMM_SMEM);

    // 0) bf16 hi/lo split of X and the four weight matrices
    convert_x_kernel<<<(T_DIM * OBS) / 1024, 256>>>(x);
    convert_w_kernel<<<dim3((HID * OBS) / 1024, 4), 256>>>(W_in, W_B, W_C, W_delta);

    // 1) 4 GEMMs on tensor cores; fp16 outputs for x_state/B/C, fp32 delta_raw
    gemm_hmma_kernel<<<dim3(HID / GBN, T_DIM / GBM, 4), 128, GEMM_SMEM>>>();

    // 2+3) chunked scan; 2 channels/thread
    scan_chunk_kernel<<<dim3(HID / 512, NCHUNK), 256>>>(A_log);
    scan_agg_kernel<<<HID / 8, 256>>>();
    scan_apply_kernel<<<dim3(HID / 512, NCHUNK), 256>>>(A_log);

    // 4) output projection
    out_kernel<<<T_DIM / 8, 256>>>(x, W_out, b_out, W_skip, out);
}

// round 13
// speedup vs baseline: 1.0110x; 1.0110x over previous
#include <cuda_runtime.h>
#include <cuda_bf16.h>
#include <cuda_fp16.h>
#include <math.h>
#include <stdint.h>

#define T_DIM 8192
#define OBS 512
#define HID 2048
#define NOBJ 8

#define NCHUNK 128
#define LC (T_DIM / NCHUNK)   // 64

// ---------------------------------------------------------------------------
// Scratch (device globals; no allocation allowed).
// g_h16[0]=x_state, g_h16[1]=B, g_h16[2]=C (fp16); g_buf[3]=delta_raw (fp32);
// g_y16 = y (fp16, scan output)
__device__ float g_buf[4][(size_t)T_DIM * HID];
__device__ __half g_h16[3][(size_t)T_DIM * HID];
__device__ __half g_y16[(size_t)T_DIM * HID];
__device__ float g_aggA[NCHUNK * HID];
__device__ float g_aggB[NCHUNK * HID];
__device__ float g_hinit[NCHUNK * HID];
// bf16 hi/lo split operands
__device__ __nv_bfloat16 g_xhi[(size_t)T_DIM * OBS];
__device__ __nv_bfloat16 g_xlo[(size_t)T_DIM * OBS];
__device__ __nv_bfloat16 g_whi[4ull * HID * OBS];
__device__ __nv_bfloat16 g_wlo[4ull * HID * OBS];

// ---------------------------------------------------------------------------
__device__ __forceinline__ uint32_t smem_to_u32(const void* p) {
    uint32_t a;
    asm("{ .reg .u64 t; cvta.to.shared.u64 t, %1; cvt.u32.u64 %0, t; }" : "=r"(a) : "l"(p));
    return a;
}
__device__ __forceinline__ void cp16(uint32_t dst, const void* src) {
    asm volatile("cp.async.cg.shared.global [%0], [%1], 16;" :: "r"(dst), "l"(src));
}
__device__ __forceinline__ void cp_commit() { asm volatile("cp.async.commit_group;"); }
__device__ __forceinline__ void ldsm4(uint32_t* r, uint32_t addr) {
    asm volatile("ldmatrix.sync.aligned.m8n8.x4.shared.b16 {%0,%1,%2,%3}, [%4];"
                 : "=r"(r[0]), "=r"(r[1]), "=r"(r[2]), "=r"(r[3]) : "r"(addr));
}
__device__ __forceinline__ void mma16816(float* c, const uint32_t* a, uint32_t b0, uint32_t b1) {
    asm volatile(
        "mma.sync.aligned.m16n8k16.row.col.f32.bf16.bf16.f32 "
        "{%0,%1,%2,%3}, {%4,%5,%6,%7}, {%8,%9}, {%0,%1,%2,%3};"
        : "+f"(c[0]), "+f"(c[1]), "+f"(c[2]), "+f"(c[3])
        : "r"(a[0]), "r"(a[1]), "r"(a[2]), "r"(a[3]), "r"(b0), "r"(b1));
}
__device__ __forceinline__ uint32_t pack_bf16x2(float a, float b) {
    __nv_bfloat162 p = __floats2bfloat162_rn(a, b);
    return *(uint32_t*)&p;
}

// ---------------------------------------------------------------------------
// fp32 -> bf16 hi/lo conversion (vectorized)
// ---------------------------------------------------------------------------
__global__ void convert_x_kernel(const float* __restrict__ x) {
    size_t i = ((size_t)blockIdx.x * blockDim.x + threadIdx.x) * 4;
    float4 v = *(const float4*)(x + i);
    __nv_bfloat16 h0 = __float2bfloat16(v.x), h1 = __float2bfloat16(v.y);
    __nv_bfloat16 h2 = __float2bfloat16(v.z), h3 = __float2bfloat16(v.w);
    uint2 hp;
    hp.x = pack_bf16x2(__bfloat162float(h0), __bfloat162float(h1));
    hp.y = pack_bf16x2(__bfloat162float(h2), __bfloat162float(h3));
    *(uint2*)(g_xhi + i) = hp;
    uint2 lp;
    lp.x = pack_bf16x2(v.x - __bfloat162float(h0), v.y - __bfloat162float(h1));
    lp.y = pack_bf16x2(v.z - __bfloat162float(h2), v.w - __bfloat162float(h3));
    *(uint2*)(g_xlo + i) = lp;
}
__global__ void convert_w_kernel(const float* __restrict__ w0, const float* __restrict__ w1,
                                 const float* __restrict__ w2, const float* __restrict__ w3) {
    int z = blockIdx.y;
    const float* __restrict__ W = (z == 0) ? w0 : (z == 1) ? w1 : (z == 2) ? w2 : w3;
    size_t i = ((size_t)blockIdx.x * blockDim.x + threadIdx.x) * 4;
    float4 v = *(const float4*)(W + i);
    size_t o = (size_t)z * HID * OBS + i;
    __nv_bfloat16 h0 = __float2bfloat16(v.x), h1 = __float2bfloat16(v.y);
    __nv_bfloat16 h2 = __float2bfloat16(v.z), h3 = __float2bfloat16(v.w);
    uint2 hp;
    hp.x = pack_bf16x2(__bfloat162float(h0), __bfloat162float(h1));
    hp.y = pack_bf16x2(__bfloat162float(h2), __bfloat162float(h3));
    *(uint2*)(g_whi + o) = hp;
    uint2 lp;
    lp.x = pack_bf16x2(v.x - __bfloat162float(h0), v.y - __bfloat162float(h1));
    lp.y = pack_bf16x2(v.z - __bfloat162float(h2), v.w - __bfloat162float(h3));
    *(uint2*)(g_wlo + o) = lp;
}

// ---------------------------------------------------------------------------
// HMMA GEMM (proven ~122us/GEMM): G[z] = X . W_z^T, bf16 3-term hi/lo.
// BM=128, BN=128, BK=32. 4 warps 2x2, warp tile 64x64. 128 thr, 2 CTAs/SM.
// Epilogue: z<3 stores fp16 (x_state,B,C); z==3 stores fp32 delta_raw.
// ---------------------------------------------------------------------------
#define GBM 128
#define GBN 128
#define GBK 32
#define NS (OBS / GBK)           // 16
#define ROWB 80
#define A_BYTES (GBM * ROWB)     // 10240
#define B_BYTES (GBN * ROWB)     // 10240
#define STAGE_BYTES (2 * A_BYTES + 2 * B_BYTES)   // 40960
#define GEMM_SMEM (2 * STAGE_BYTES)               // 81920

__global__ __launch_bounds__(128, 2)
void gemm_hmma_kernel() {
    extern __shared__ char smem[];
    const uint32_t sbase = smem_to_u32(smem);
    const int tid = threadIdx.x;
    const int wid = tid >> 5;
    const int lane = tid & 31;
    const int wm = wid >> 1;         // 0..1 -> m offset *64
    const int wn = wid & 1;          // 0..1 -> n offset *64

    const int z = blockIdx.z;
    const int n0 = blockIdx.x * GBN;
    const int m0 = blockIdx.y * GBM;
    const __nv_bfloat16* __restrict__ whi = g_whi + (size_t)z * HID * OBS;
    const __nv_bfloat16* __restrict__ wlo = g_wlo + (size_t)z * HID * OBS;

    float acc[4][8][4];   // [mi][n8-frag][frag]
#pragma unroll
    for (int i = 0; i < 4; i++)
#pragma unroll
        for (int j = 0; j < 8; j++)
#pragma unroll
            for (int k = 0; k < 4; k++) acc[i][j][k] = 0.f;

    auto load_stage = [&](int s, int bi) {
        const int k0 = s * GBK;
        const uint32_t st = sbase + bi * STAGE_BYTES;
#pragma unroll
        for (int i = 0; i < 4; i++) {
            int idx = tid + 128 * i;          // 0..511
            int row = idx >> 2, c = idx & 3;
            size_t gsrc = (size_t)(m0 + row) * OBS + k0 + c * 8;
            uint32_t dst = st + row * ROWB + c * 16;
            cp16(dst,           g_xhi + gsrc);
            cp16(dst + A_BYTES, g_xlo + gsrc);
        }
#pragma unroll
        for (int i = 0; i < 4; i++) {
            int idx = tid + 128 * i;
            int row = idx >> 2, c = idx & 3;
            size_t gsrc = (size_t)(n0 + row) * OBS + k0 + c * 8;
            uint32_t dst = st + 2 * A_BYTES + row * ROWB + c * 16;
            cp16(dst,           whi + gsrc);
            cp16(dst + B_BYTES, wlo + gsrc);
        }
        cp_commit();
    };

    load_stage(0, 0);

    for (int s = 0; s < NS; s++) {
        if (s + 1 < NS) {
            load_stage(s + 1, (s + 1) & 1);
            asm volatile("cp.async.wait_group 1;" ::: "memory");
        } else {
            asm volatile("cp.async.wait_group 0;" ::: "memory");
        }
        __syncthreads();

        const uint32_t ab = sbase + (s & 1) * STAGE_BYTES;   // A hi
        const uint32_t bb = ab + 2 * A_BYTES;                // B hi

#pragma unroll
        for (int ks = 0; ks < 2; ks++) {
            uint32_t ahi[4][4], alo[4][4];
#pragma unroll
            for (int mi = 0; mi < 4; mi++) {
                uint32_t addr = ab + (wm * 64 + mi * 16 + (lane & 15)) * ROWB
                              + ks * 32 + (lane >> 4) * 16;
                ldsm4(ahi[mi], addr);
                ldsm4(alo[mi], addr + A_BYTES);
            }
            uint32_t bhi[4][4], blo[4][4];
#pragma unroll
            for (int np = 0; np < 4; np++) {
                uint32_t addr = bb + (wn * 64 + np * 16 + (lane >> 4) * 8 + (lane & 7)) * ROWB
                              + ks * 32 + ((lane >> 3) & 1) * 16;
                ldsm4(bhi[np], addr);
                ldsm4(blo[np], addr + B_BYTES);
            }
#pragma unroll
            for (int mi = 0; mi < 4; mi++)
#pragma unroll
                for (int np = 0; np < 4; np++) {
                    mma16816(acc[mi][np * 2],     ahi[mi], bhi[np][0], bhi[np][1]);
                    mma16816(acc[mi][np * 2 + 1], ahi[mi], bhi[np][2], bhi[np][3]);
                }
#pragma unroll
            for (int mi = 0; mi < 4; mi++)
#pragma unroll
                for (int np = 0; np < 4; np++) {
                    mma16816(acc[mi][np * 2],     ahi[mi], blo[np][0], blo[np][1]);
                    mma16816(acc[mi][np * 2 + 1], ahi[mi], blo[np][2], blo[np][3]);
                }
#pragma unroll
            for (int mi = 0; mi < 4; mi++)
#pragma unroll
                for (int np = 0; np < 4; np++) {
                    mma16816(acc[mi][np * 2],     alo[mi], bhi[np][0], bhi[np][1]);
                    mma16816(acc[mi][np * 2 + 1], alo[mi], bhi[np][2], bhi[np][3]);
                }
        }
        __syncthreads();
    }

    // Epilogue: z<3 -> fp16; z==3 (delta_raw) -> fp32
    if (z == 3) {
        float* __restrict__ G = g_buf[3];
#pragma unroll
        for (int mi = 0; mi < 4; mi++) {
            int row = m0 + wm * 64 + mi * 16 + (lane >> 2);
#pragma unroll
            for (int ni = 0; ni < 8; ni++) {
                int col = n0 + wn * 64 + ni * 8 + (lane & 3) * 2;
                *(float2*)(G + (size_t)row * HID + col) =
                    make_float2(acc[mi][ni][0], acc[mi][ni][1]);
                *(float2*)(G + (size_t)(row + 8) * HID + col) =
                    make_float2(acc[mi][ni][2], acc[mi][ni][3]);
            }
        }
    } else {
        __half* __restrict__ H = g_h16[z];
#pragma unroll
        for (int mi = 0; mi < 4; mi++) {
            int row = m0 + wm * 64 + mi * 16 + (lane >> 2);
#pragma unroll
            for (int ni = 0; ni < 8; ni++) {
                int col = n0 + wn * 64 + ni * 8 + (lane & 3) * 2;
                *(__half2*)(H + (size_t)row * HID + col) =
                    __floats2half2_rn(acc[mi][ni][0], acc[mi][ni][1]);
                *(__half2*)(H + (size_t)(row + 8) * HID + col) =
                    __floats2half2_rn(acc[mi][ni][2], acc[mi][ni][3]);
            }
        }
    }
}

// ---------------------------------------------------------------------------
// Scan pass 1: per-chunk aggregates only (scalar, 1024 blocks — proven config).
// ---------------------------------------------------------------------------
__global__ void scan_chunk_kernel(const float* __restrict__ A_log) {
    int h = blockIdx.x * blockDim.x + threadIdx.x;
    int c = blockIdx.y;
    float A = -expf(A_log[h]);
    size_t base = (size_t)(c * LC) * HID + h;
    float ap = 1.f, bb = 0.f;
#pragma unroll 4
    for (int i = 0; i < LC; i++) {
        float dr = g_buf[3][base];
        float xs = __half2float(g_h16[0][base]);
        float Bv = __half2float(g_h16[1][base]);
        float delta = 1.f / (1.f + __expf(-dr));
        float a = expf(delta * A);
        float bx = Bv * xs;
        ap *= a;
        bb = a * bb + bx;
        base += HID;
    }
    g_aggA[c * HID + h] = ap;
    g_aggB[c * HID + h] = bb;
}

// ---------------------------------------------------------------------------
// Scan pass 2: warp-parallel scan of NCHUNK aggregates per channel.
// ---------------------------------------------------------------------------
__global__ void scan_agg_kernel() {
    int warp = threadIdx.x >> 5;
    int lane = threadIdx.x & 31;
    int h = blockIdx.x * 8 + warp;

    float a_loc[4], b_loc[4];
    float ca = 1.f, cb = 0.f;
    int cbase = lane * 4;
#pragma unroll
    for (int j = 0; j < 4; j++) {
        float a = g_aggA[(cbase + j) * HID + h];
        float b = g_aggB[(cbase + j) * HID + h];
        a_loc[j] = a; b_loc[j] = b;
        cb = a * cb + b;
        ca *= a;
    }
    float ia = ca, ib = cb;
#pragma unroll
    for (int off = 1; off < 32; off <<= 1) {
        float pa = __shfl_up_sync(0xFFFFFFFFu, ia, off);
        float pb = __shfl_up_sync(0xFFFFFFFFu, ib, off);
        if (lane >= off) {
            ib = ia * pb + ib;
            ia = ia * pa;
        }
    }
    float eb = __shfl_up_sync(0xFFFFFFFFu, ib, 1);
    if (lane == 0) eb = 0.f;
    float hcur = eb;
#pragma unroll
    for (int j = 0; j < 4; j++) {
        g_hinit[(cbase + j) * HID + h] = hcur;
        hcur = a_loc[j] * hcur + b_loc[j];
    }
}

// ---------------------------------------------------------------------------
// Scan pass 3: apply within chunk (scalar); y = C*h stored as fp16.
// ---------------------------------------------------------------------------
__global__ void scan_apply_kernel(const float* __restrict__ A_log) {
    int h = blockIdx.x * blockDim.x + threadIdx.x;
    int c = blockIdx.y;
    float A = -expf(A_log[h]);
    size_t base = (size_t)(c * LC) * HID + h;
    float hs = g_hinit[c * HID + h];
#pragma unroll 4
    for (int i = 0; i < LC; i++) {
        float dr = g_buf[3][base];
        float xs = __half2float(g_h16[0][base]);
        float Bv = __half2float(g_h16[1][base]);
        float Cv = __half2float(g_h16[2][base]);
        float delta = 1.f / (1.f + __expf(-dr));
        float a = expf(delta * A);
        hs = a * hs + Bv * xs;
        g_y16[base] = __float2half_rn(Cv * hs);
        base += HID;
    }
}

// ---------------------------------------------------------------------------
// Output projection: warp per timestep; y read as fp16.
// ---------------------------------------------------------------------------
__global__ void out_kernel(const float* __restrict__ x,
                           const float* __restrict__ W_out,
                           const float* __restrict__ b_out,
                           const float* __restrict__ W_skip,
                           float* __restrict__ out) {
    int warp = threadIdx.x >> 5;
    int lane = threadIdx.x & 31;
    int t = blockIdx.x * (blockDim.x >> 5) + warp;
    if (t >= T_DIM) return;

    float acc[NOBJ];
#pragma unroll
    for (int n = 0; n < NOBJ; n++) acc[n] = 0.f;

    const __half* yrow = g_y16 + (size_t)t * HID;
    for (int h = lane; h < HID; h += 32) {
        float yv = __half2float(yrow[h]);
#pragma unroll
        for (int n = 0; n < NOBJ; n++) acc[n] += yv * W_out[n * HID + h];
    }
    const float* xrow = x + (size_t)t * OBS;
    for (int o = lane; o < OBS; o += 32) {
        float xv = xrow[o];
#pragma unroll
        for (int n = 0; n < NOBJ; n++) acc[n] += xv * W_skip[n * OBS + o];
    }
#pragma unroll
    for (int n = 0; n < NOBJ; n++) {
#pragma unroll
        for (int off = 16; off > 0; off >>= 1)
            acc[n] += __shfl_down_sync(0xFFFFFFFFu, acc[n], off);
    }
    if (lane == 0) {
#pragma unroll
        for (int n = 0; n < NOBJ; n++)
            out[(size_t)t * NOBJ + n] = acc[n] + b_out[n];
    }
}

// ---------------------------------------------------------------------------
extern "C" void kernel_launch(void* const* d_in, const int* in_sizes, int n_in,
                              void* d_out, int out_size) {
    const float* x       = (const float*)d_in[0];
    const float* W_in    = (const float*)d_in[1];
    const float* W_B     = (const float*)d_in[2];
    const float* W_C     = (const float*)d_in[3];
    const float* W_delta = (const float*)d_in[4];
    const float* A_log   = (const float*)d_in[5];
    const float* W_out   = (const float*)d_in[6];
    const float* b_out   = (const float*)d_in[7];
    const float* W_skip  = (const float*)d_in[8];
    float* out = (float*)d_out;

    cudaFuncSetAttribute(gemm_hmma_kernel, cudaFuncAttributeMaxDynamicSharedMemorySize, GEMM_SMEM);

    // 0) bf16 hi/lo split of X and the four weight matrices
    convert_x_kernel<<<(T_DIM * OBS) / 1024, 256>>>(x);
    convert_w_kernel<<<dim3((HID * OBS) / 1024, 4), 256>>>(W_in, W_B, W_C, W_delta);

    // 1) 4 GEMMs on tensor cores; fp16 outputs for x_state/B/C, fp32 delta_raw
    gemm_hmma_kernel<<<dim3(HID / GBN, T_DIM / GBM, 4), 128, GEMM_SMEM>>>();

    // 2+3) chunked scan (scalar, 1024-block config — proven)
    scan_chunk_kernel<<<dim3(HID / 256, NCHUNK), 256>>>(A_log);
    scan_agg_kernel<<<HID / 8, 256>>>();
    scan_apply_kernel<<<dim3(HID / 256, NCHUNK), 256>>>(A_log);

    // 4) output projection
    out_kernel<<<T_DIM / 8, 256>>>(x, W_out, b_out, W_skip, out);
}

// round 15
// speedup vs baseline: 1.4791x; 1.4630x over previous
#include <cuda_runtime.h>
#include <cuda_bf16.h>
#include <cuda_fp16.h>
#include <math.h>
#include <stdint.h>

#define T_DIM 8192
#define OBS 512
#define HID 2048
#define NOBJ 8

#define NCHUNK 128
#define LC (T_DIM / NCHUNK)   // 64

// ---------------------------------------------------------------------------
// Scratch (device globals; no allocation allowed).
// g_h16[0]=x_state, g_h16[1]=B, g_h16[2]=C (fp16); g_buf[3]=delta_raw (fp32);
// g_buf[0]=y (fp32, scan output)
__device__ float g_buf[4][(size_t)T_DIM * HID];
__device__ __half g_h16[3][(size_t)T_DIM * HID];
__device__ float g_aggA[NCHUNK * HID];
__device__ float g_aggB[NCHUNK * HID];
__device__ float g_hinit[NCHUNK * HID];
// bf16 hi/lo split operands
__device__ __nv_bfloat16 g_xhi[(size_t)T_DIM * OBS];
__device__ __nv_bfloat16 g_xlo[(size_t)T_DIM * OBS];
__device__ __nv_bfloat16 g_whi[4ull * HID * OBS];
__device__ __nv_bfloat16 g_wlo[4ull * HID * OBS];

// ---------------------------------------------------------------------------
__device__ __forceinline__ uint32_t smem_to_u32(const void* p) {
    uint32_t a;
    asm("{ .reg .u64 t; cvta.to.shared.u64 t, %1; cvt.u32.u64 %0, t; }" : "=r"(a) : "l"(p));
    return a;
}
__device__ __forceinline__ void cp16(uint32_t dst, const void* src) {
    asm volatile("cp.async.cg.shared.global [%0], [%1], 16;" :: "r"(dst), "l"(src));
}
__device__ __forceinline__ void cp_commit() { asm volatile("cp.async.commit_group;"); }
__device__ __forceinline__ void ldsm4(uint32_t* r, uint32_t addr) {
    asm volatile("ldmatrix.sync.aligned.m8n8.x4.shared.b16 {%0,%1,%2,%3}, [%4];"
                 : "=r"(r[0]), "=r"(r[1]), "=r"(r[2]), "=r"(r[3]) : "r"(addr));
}
__device__ __forceinline__ void mma16816(float* c, const uint32_t* a, uint32_t b0, uint32_t b1) {
    asm volatile(
        "mma.sync.aligned.m16n8k16.row.col.f32.bf16.bf16.f32 "
        "{%0,%1,%2,%3}, {%4,%5,%6,%7}, {%8,%9}, {%0,%1,%2,%3};"
        : "+f"(c[0]), "+f"(c[1]), "+f"(c[2]), "+f"(c[3])
        : "r"(a[0]), "r"(a[1]), "r"(a[2]), "r"(a[3]), "r"(b0), "r"(b1));
}
__device__ __forceinline__ uint32_t pack_bf16x2(float a, float b) {
    __nv_bfloat162 p = __floats2bfloat162_rn(a, b);
    return *(uint32_t*)&p;
}

// ---------------------------------------------------------------------------
// fp32 -> bf16 hi/lo conversion (vectorized)
// ---------------------------------------------------------------------------
__global__ void convert_x_kernel(const float* __restrict__ x) {
    size_t i = ((size_t)blockIdx.x * blockDim.x + threadIdx.x) * 4;
    float4 v = *(const float4*)(x + i);
    __nv_bfloat16 h0 = __float2bfloat16(v.x), h1 = __float2bfloat16(v.y);
    __nv_bfloat16 h2 = __float2bfloat16(v.z), h3 = __float2bfloat16(v.w);
    uint2 hp;
    hp.x = pack_bf16x2(__bfloat162float(h0), __bfloat162float(h1));
    hp.y = pack_bf16x2(__bfloat162float(h2), __bfloat162float(h3));
    *(uint2*)(g_xhi + i) = hp;
    uint2 lp;
    lp.x = pack_bf16x2(v.x - __bfloat162float(h0), v.y - __bfloat162float(h1));
    lp.y = pack_bf16x2(v.z - __bfloat162float(h2), v.w - __bfloat162float(h3));
    *(uint2*)(g_xlo + i) = lp;
}
__global__ void convert_w_kernel(const float* __restrict__ w0, const float* __restrict__ w1,
                                 const float* __restrict__ w2, const float* __restrict__ w3) {
    int z = blockIdx.y;
    const float* __restrict__ W = (z == 0) ? w0 : (z == 1) ? w1 : (z == 2) ? w2 : w3;
    size_t i = ((size_t)blockIdx.x * blockDim.x + threadIdx.x) * 4;
    float4 v = *(const float4*)(W + i);
    size_t o = (size_t)z * HID * OBS + i;
    __nv_bfloat16 h0 = __float2bfloat16(v.x), h1 = __float2bfloat16(v.y);
    __nv_bfloat16 h2 = __float2bfloat16(v.z), h3 = __float2bfloat16(v.w);
    uint2 hp;
    hp.x = pack_bf16x2(__bfloat162float(h0), __bfloat162float(h1));
    hp.y = pack_bf16x2(__bfloat162float(h2), __bfloat162float(h3));
    *(uint2*)(g_whi + o) = hp;
    uint2 lp;
    lp.x = pack_bf16x2(v.x - __bfloat162float(h0), v.y - __bfloat162float(h1));
    lp.y = pack_bf16x2(v.z - __bfloat162float(h2), v.w - __bfloat162float(h3));
    *(uint2*)(g_wlo + o) = lp;
}

// ---------------------------------------------------------------------------
// HMMA GEMM (proven ~122us/GEMM): G[z] = X . W_z^T, bf16 3-term hi/lo.
// BM=128, BN=128, BK=32. 4 warps 2x2, warp tile 64x64. 128 thr, 2 CTAs/SM.
// Epilogue: z<3 stores fp16 (x_state,B,C); z==3 stores fp32 delta_raw.
// ---------------------------------------------------------------------------
#define GBM 128
#define GBN 128
#define GBK 32
#define NS (OBS / GBK)           // 16
#define ROWB 80
#define A_BYTES (GBM * ROWB)     // 10240
#define B_BYTES (GBN * ROWB)     // 10240
#define STAGE_BYTES (2 * A_BYTES + 2 * B_BYTES)   // 40960
#define GEMM_SMEM (2 * STAGE_BYTES)               // 81920

__global__ __launch_bounds__(128, 2)
void gemm_hmma_kernel() {
    extern __shared__ char smem[];
    const uint32_t sbase = smem_to_u32(smem);
    const int tid = threadIdx.x;
    const int wid = tid >> 5;
    const int lane = tid & 31;
    const int wm = wid >> 1;         // 0..1 -> m offset *64
    const int wn = wid & 1;          // 0..1 -> n offset *64

    const int z = blockIdx.z;
    const int n0 = blockIdx.x * GBN;
    const int m0 = blockIdx.y * GBM;
    const __nv_bfloat16* __restrict__ whi = g_whi + (size_t)z * HID * OBS;
    const __nv_bfloat16* __restrict__ wlo = g_wlo + (size_t)z * HID * OBS;

    float acc[4][8][4];   // [mi][n8-frag][frag]
#pragma unroll
    for (int i = 0; i < 4; i++)
#pragma unroll
        for (int j = 0; j < 8; j++)
#pragma unroll
            for (int k = 0; k < 4; k++) acc[i][j][k] = 0.f;

    auto load_stage = [&](int s, int bi) {
        const int k0 = s * GBK;
        const uint32_t st = sbase + bi * STAGE_BYTES;
#pragma unroll
        for (int i = 0; i < 4; i++) {
            int idx = tid + 128 * i;          // 0..511
            int row = idx >> 2, c = idx & 3;
            size_t gsrc = (size_t)(m0 + row) * OBS + k0 + c * 8;
            uint32_t dst = st + row * ROWB + c * 16;
            cp16(dst,           g_xhi + gsrc);
            cp16(dst + A_BYTES, g_xlo + gsrc);
        }
#pragma unroll
        for (int i = 0; i < 4; i++) {
            int idx = tid + 128 * i;
            int row = idx >> 2, c = idx & 3;
            size_t gsrc = (size_t)(n0 + row) * OBS + k0 + c * 8;
            uint32_t dst = st + 2 * A_BYTES + row * ROWB + c * 16;
            cp16(dst,           whi + gsrc);
            cp16(dst + B_BYTES, wlo + gsrc);
        }
        cp_commit();
    };

    load_stage(0, 0);

    for (int s = 0; s < NS; s++) {
        if (s + 1 < NS) {
            load_stage(s + 1, (s + 1) & 1);
            asm volatile("cp.async.wait_group 1;" ::: "memory");
        } else {
            asm volatile("cp.async.wait_group 0;" ::: "memory");
        }
        __syncthreads();

        const uint32_t ab = sbase + (s & 1) * STAGE_BYTES;   // A hi
        const uint32_t bb = ab + 2 * A_BYTES;                // B hi

#pragma unroll
        for (int ks = 0; ks < 2; ks++) {
            uint32_t ahi[4][4], alo[4][4];
#pragma unroll
            for (int mi = 0; mi < 4; mi++) {
                uint32_t addr = ab + (wm * 64 + mi * 16 + (lane & 15)) * ROWB
                              + ks * 32 + (lane >> 4) * 16;
                ldsm4(ahi[mi], addr);
                ldsm4(alo[mi], addr + A_BYTES);
            }
            uint32_t bhi[4][4], blo[4][4];
#pragma unroll
            for (int np = 0; np < 4; np++) {
                uint32_t addr = bb + (wn * 64 + np * 16 + (lane >> 4) * 8 + (lane & 7)) * ROWB
                              + ks * 32 + ((lane >> 3) & 1) * 16;
                ldsm4(bhi[np], addr);
                ldsm4(blo[np], addr + B_BYTES);
            }
#pragma unroll
            for (int mi = 0; mi < 4; mi++)
#pragma unroll
                for (int np = 0; np < 4; np++) {
                    mma16816(acc[mi][np * 2],     ahi[mi], bhi[np][0], bhi[np][1]);
                    mma16816(acc[mi][np * 2 + 1], ahi[mi], bhi[np][2], bhi[np][3]);
                }
#pragma unroll
            for (int mi = 0; mi < 4; mi++)
#pragma unroll
                for (int np = 0; np < 4; np++) {
                    mma16816(acc[mi][np * 2],     ahi[mi], blo[np][0], blo[np][1]);
                    mma16816(acc[mi][np * 2 + 1], ahi[mi], blo[np][2], blo[np][3]);
                }
#pragma unroll
            for (int mi = 0; mi < 4; mi++)
#pragma unroll
                for (int np = 0; np < 4; np++) {
                    mma16816(acc[mi][np * 2],     alo[mi], bhi[np][0], bhi[np][1]);
                    mma16816(acc[mi][np * 2 + 1], alo[mi], bhi[np][2], bhi[np][3]);
                }
        }
        __syncthreads();
    }

    // Epilogue: z<3 -> fp16; z==3 (delta_raw) -> fp32
    if (z == 3) {
        float* __restrict__ G = g_buf[3];
#pragma unroll
        for (int mi = 0; mi < 4; mi++) {
            int row = m0 + wm * 64 + mi * 16 + (lane >> 2);
#pragma unroll
            for (int ni = 0; ni < 8; ni++) {
                int col = n0 + wn * 64 + ni * 8 + (lane & 3) * 2;
                *(float2*)(G + (size_t)row * HID + col) =
                    make_float2(acc[mi][ni][0], acc[mi][ni][1]);
                *(float2*)(G + (size_t)(row + 8) * HID + col) =
                    make_float2(acc[mi][ni][2], acc[mi][ni][3]);
            }
        }
    } else {
        __half* __restrict__ H = g_h16[z];
#pragma unroll
        for (int mi = 0; mi < 4; mi++) {
            int row = m0 + wm * 64 + mi * 16 + (lane >> 2);
#pragma unroll
            for (int ni = 0; ni < 8; ni++) {
                int col = n0 + wn * 64 + ni * 8 + (lane & 3) * 2;
                *(__half2*)(H + (size_t)row * HID + col) =
                    __floats2half2_rn(acc[mi][ni][0], acc[mi][ni][1]);
                *(__half2*)(H + (size_t)(row + 8) * HID + col) =
                    __floats2half2_rn(acc[mi][ni][2], acc[mi][ni][3]);
            }
        }
    }
}

// ---------------------------------------------------------------------------
// Scan pass 1: per-chunk aggregates only (no stores back).
// a and bx computed on the fly from fp16 xs/B and fp32 delta_raw.
// ---------------------------------------------------------------------------
__global__ void scan_chunk_kernel(const float* __restrict__ A_log) {
    int h = blockIdx.x * blockDim.x + threadIdx.x;
    int c = blockIdx.y;
    float A = -expf(A_log[h]);
    size_t base = (size_t)(c * LC) * HID + h;
    float ap = 1.f, bb = 0.f;
#pragma unroll 4
    for (int i = 0; i < LC; i++) {
        float dr = g_buf[3][base];
        float xs = __half2float(g_h16[0][base]);
        float Bv = __half2float(g_h16[1][base]);
        float delta = 1.f / (1.f + __expf(-dr));
        float a = expf(delta * A);
        float bx = Bv * xs;
        ap *= a;
        bb = a * bb + bx;
        base += HID;
    }
    g_aggA[c * HID + h] = ap;
    g_aggB[c * HID + h] = bb;
}

// ---------------------------------------------------------------------------
// Scan pass 2: warp-parallel scan of NCHUNK aggregates per channel.
// ---------------------------------------------------------------------------
__global__ void scan_agg_kernel() {
    int warp = threadIdx.x >> 5;
    int lane = threadIdx.x & 31;
    int h = blockIdx.x * 8 + warp;

    float a_loc[4], b_loc[4];
    float ca = 1.f, cb = 0.f;
    int cbase = lane * 4;
#pragma unroll
    for (int j = 0; j < 4; j++) {
        float a = g_aggA[(cbase + j) * HID + h];
        float b = g_aggB[(cbase + j) * HID + h];
        a_loc[j] = a; b_loc[j] = b;
        cb = a * cb + b;
        ca *= a;
    }
    float ia = ca, ib = cb;
#pragma unroll
    for (int off = 1; off < 32; off <<= 1) {
        float pa = __shfl_up_sync(0xFFFFFFFFu, ia, off);
        float pb = __shfl_up_sync(0xFFFFFFFFu, ib, off);
        if (lane >= off) {
            ib = ia * pb + ib;
            ia = ia * pa;
        }
    }
    float eb = __shfl_up_sync(0xFFFFFFFFu, ib, 1);
    if (lane == 0) eb = 0.f;
    float hcur = eb;
#pragma unroll
    for (int j = 0; j < 4; j++) {
        g_hinit[(cbase + j) * HID + h] = hcur;
        hcur = a_loc[j] * hcur + b_loc[j];
    }
}

// ---------------------------------------------------------------------------
// Scan pass 3: apply within chunk; recompute a, bx; y = C * h -> g_buf[0]
// ---------------------------------------------------------------------------
__global__ void scan_apply_kernel(const float* __restrict__ A_log) {
    int h = blockIdx.x * blockDim.x + threadIdx.x;
    int c = blockIdx.y;
    float A = -expf(A_log[h]);
    size_t base = (size_t)(c * LC) * HID + h;
    float hs = g_hinit[c * HID + h];
#pragma unroll 4
    for (int i = 0; i < LC; i++) {
        float dr = g_buf[3][base];
        float xs = __half2float(g_h16[0][base]);
        float Bv = __half2float(g_h16[1][base]);
        float Cv = __half2float(g_h16[2][base]);
        float delta = 1.f / (1.f + __expf(-dr));
        float a = expf(delta * A);
        hs = a * hs + Bv * xs;
        g_buf[0][base] = Cv * hs;
        base += HID;
    }
}

// ---------------------------------------------------------------------------
// Output projection: warp per timestep.
// ---------------------------------------------------------------------------
__global__ void out_kernel(const float* __restrict__ x,
                           const float* __restrict__ W_out,
                           const float* __restrict__ b_out,
                           const float* __restrict__ W_skip,
                           float* __restrict__ out) {
    int warp = threadIdx.x >> 5;
    int lane = threadIdx.x & 31;
    int t = blockIdx.x * (blockDim.x >> 5) + warp;
    if (t >= T_DIM) return;

    float acc[NOBJ];
#pragma unroll
    for (int n = 0; n < NOBJ; n++) acc[n] = 0.f;

    const float* yrow = g_buf[0] + (size_t)t * HID;
    for (int h = lane; h < HID; h += 32) {
        float yv = yrow[h];
#pragma unroll
        for (int n = 0; n < NOBJ; n++) acc[n] += yv * W_out[n * HID + h];
    }
    const float* xrow = x + (size_t)t * OBS;
    for (int o = lane; o < OBS; o += 32) {
        float xv = xrow[o];
#pragma unroll
        for (int n = 0; n < NOBJ; n++) acc[n] += xv * W_skip[n * OBS + o];
    }
#pragma unroll
    for (int n = 0; n < NOBJ; n++) {
#pragma unroll
        for (int off = 16; off > 0; off >>= 1)
            acc[n] += __shfl_down_sync(0xFFFFFFFFu, acc[n], off);
    }
    if (lane == 0) {
#pragma unroll
        for (int n = 0; n < NOBJ; n++)
            out[(size_t)t * NOBJ + n] = acc[n] + b_out[n];
    }
}

// ---------------------------------------------------------------------------
extern "C" void kernel_launch(void* const* d_in, const int* in_sizes, int n_in,
                              void* d_out, int out_size) {
    const float* x       = (const float*)d_in[0];
    const float* W_in    = (const float*)d_in[1];
    const float* W_B     = (const float*)d_in[2];
    const float* W_C     = (const float*)d_in[3];
    const float* W_delta = (const float*)d_in[4];
    const float* A_log   = (const float*)d_in[5];
    const float* W_out   = (const float*)d_in[6];
    const float* b_out   = (const float*)d_in[7];
    const float* W_skip  = (const float*)d_in[8];
    float* out = (float*)d_out;

    cudaFuncSetAttribute(gemm_hmma_kernel, cudaFuncAttributeMaxDynamicSharedMemorySize, GEMM_SMEM);

    // 0) bf16 hi/lo split of X and the four weight matrices
    convert_x_kernel<<<(T_DIM * OBS) / 1024, 256>>>(x);
    convert_w_kernel<<<dim3((HID * OBS) / 1024, 4), 256>>>(W_in, W_B, W_C, W_delta);

    // 1) 4 GEMMs on tensor cores; fp16 outputs for x_state/B/C, fp32 delta_raw
    gemm_hmma_kernel<<<dim3(HID / GBN, T_DIM / GBM, 4), 128, GEMM_SMEM>>>();

    // 2+3) chunked scan; a/bx recomputed from compact intermediates
    scan_chunk_kernel<<<dim3(HID / 256, NCHUNK), 256>>>(A_log);
    scan_agg_kernel<<<HID / 8, 256>>>();
    scan_apply_kernel<<<dim3(HID / 256, NCHUNK), 256>>>(A_log);

    // 4) output projection
    out_kernel<<<T_DIM / 8, 256>>>(x, W_out, b_out, W_skip, out);
}

// round 16
// speedup vs baseline: 1.4977x; 1.0126x over previous
#include <cuda_runtime.h>
#include <cuda_bf16.h>
#include <cuda_fp16.h>
#include <math.h>
#include <stdint.h>

#define T_DIM 8192
#define OBS 512
#define HID 2048
#define NOBJ 8

#define NCHUNK 128
#define LC (T_DIM / NCHUNK)   // 64

// ---------------------------------------------------------------------------
// Scratch (device globals; no allocation allowed).
// g_h16[0]=x_state, g_h16[1]=B, g_h16[2]=C (fp16); g_buf[3]=delta_raw (fp32);
// g_y16 = y (fp16, scan output)
__device__ float g_buf[4][(size_t)T_DIM * HID];
__device__ __half g_h16[3][(size_t)T_DIM * HID];
__device__ __half g_y16[(size_t)T_DIM * HID];
__device__ float g_aggA[NCHUNK * HID];
__device__ float g_aggB[NCHUNK * HID];
__device__ float g_hinit[NCHUNK * HID];
// bf16 hi/lo split operands
__device__ __nv_bfloat16 g_xhi[(size_t)T_DIM * OBS];
__device__ __nv_bfloat16 g_xlo[(size_t)T_DIM * OBS];
__device__ __nv_bfloat16 g_whi[4ull * HID * OBS];
__device__ __nv_bfloat16 g_wlo[4ull * HID * OBS];

// ---------------------------------------------------------------------------
__device__ __forceinline__ uint32_t smem_to_u32(const void* p) {
    uint32_t a;
    asm("{ .reg .u64 t; cvta.to.shared.u64 t, %1; cvt.u32.u64 %0, t; }" : "=r"(a) : "l"(p));
    return a;
}
__device__ __forceinline__ void cp16(uint32_t dst, const void* src) {
    asm volatile("cp.async.cg.shared.global [%0], [%1], 16;" :: "r"(dst), "l"(src));
}
__device__ __forceinline__ void cp_commit() { asm volatile("cp.async.commit_group;"); }
__device__ __forceinline__ void ldsm4(uint32_t* r, uint32_t addr) {
    asm volatile("ldmatrix.sync.aligned.m8n8.x4.shared.b16 {%0,%1,%2,%3}, [%4];"
                 : "=r"(r[0]), "=r"(r[1]), "=r"(r[2]), "=r"(r[3]) : "r"(addr));
}
__device__ __forceinline__ void mma16816(float* c, const uint32_t* a, uint32_t b0, uint32_t b1) {
    asm volatile(
        "mma.sync.aligned.m16n8k16.row.col.f32.bf16.bf16.f32 "
        "{%0,%1,%2,%3}, {%4,%5,%6,%7}, {%8,%9}, {%0,%1,%2,%3};"
        : "+f"(c[0]), "+f"(c[1]), "+f"(c[2]), "+f"(c[3])
        : "r"(a[0]), "r"(a[1]), "r"(a[2]), "r"(a[3]), "r"(b0), "r"(b1));
}
__device__ __forceinline__ uint32_t pack_bf16x2(float a, float b) {
    __nv_bfloat162 p = __floats2bfloat162_rn(a, b);
    return *(uint32_t*)&p;
}

// ---------------------------------------------------------------------------
// fp32 -> bf16 hi/lo conversion (vectorized)
// ---------------------------------------------------------------------------
__global__ void convert_x_kernel(const float* __restrict__ x) {
    size_t i = ((size_t)blockIdx.x * blockDim.x + threadIdx.x) * 4;
    float4 v = *(const float4*)(x + i);
    __nv_bfloat16 h0 = __float2bfloat16(v.x), h1 = __float2bfloat16(v.y);
    __nv_bfloat16 h2 = __float2bfloat16(v.z), h3 = __float2bfloat16(v.w);
    uint2 hp;
    hp.x = pack_bf16x2(__bfloat162float(h0), __bfloat162float(h1));
    hp.y = pack_bf16x2(__bfloat162float(h2), __bfloat162float(h3));
    *(uint2*)(g_xhi + i) = hp;
    uint2 lp;
    lp.x = pack_bf16x2(v.x - __bfloat162float(h0), v.y - __bfloat162float(h1));
    lp.y = pack_bf16x2(v.z - __bfloat162float(h2), v.w - __bfloat162float(h3));
    *(uint2*)(g_xlo + i) = lp;
}
__global__ void convert_w_kernel(const float* __restrict__ w0, const float* __restrict__ w1,
                                 const float* __restrict__ w2, const float* __restrict__ w3) {
    int z = blockIdx.y;
    const float* __restrict__ W = (z == 0) ? w0 : (z == 1) ? w1 : (z == 2) ? w2 : w3;
    size_t i = ((size_t)blockIdx.x * blockDim.x + threadIdx.x) * 4;
    float4 v = *(const float4*)(W + i);
    size_t o = (size_t)z * HID * OBS + i;
    __nv_bfloat16 h0 = __float2bfloat16(v.x), h1 = __float2bfloat16(v.y);
    __nv_bfloat16 h2 = __float2bfloat16(v.z), h3 = __float2bfloat16(v.w);
    uint2 hp;
    hp.x = pack_bf16x2(__bfloat162float(h0), __bfloat162float(h1));
    hp.y = pack_bf16x2(__bfloat162float(h2), __bfloat162float(h3));
    *(uint2*)(g_whi + o) = hp;
    uint2 lp;
    lp.x = pack_bf16x2(v.x - __bfloat162float(h0), v.y - __bfloat162float(h1));
    lp.y = pack_bf16x2(v.z - __bfloat162float(h2), v.w - __bfloat162float(h3));
    *(uint2*)(g_wlo + o) = lp;
}

// ---------------------------------------------------------------------------
// HMMA GEMM (proven ~122us/GEMM): G[z] = X . W_z^T, bf16 3-term hi/lo.
// BM=128, BN=128, BK=32. 4 warps 2x2, warp tile 64x64. 128 thr, 2 CTAs/SM.
// Epilogue: z<3 stores fp16 (x_state,B,C); z==3 stores fp32 delta_raw.
// ---------------------------------------------------------------------------
#define GBM 128
#define GBN 128
#define GBK 32
#define NS (OBS / GBK)           // 16
#define ROWB 80
#define A_BYTES (GBM * ROWB)     // 10240
#define B_BYTES (GBN * ROWB)     // 10240
#define STAGE_BYTES (2 * A_BYTES + 2 * B_BYTES)   // 40960
#define GEMM_SMEM (2 * STAGE_BYTES)               // 81920

__global__ __launch_bounds__(128, 2)
void gemm_hmma_kernel() {
    extern __shared__ char smem[];
    const uint32_t sbase = smem_to_u32(smem);
    const int tid = threadIdx.x;
    const int wid = tid >> 5;
    const int lane = tid & 31;
    const int wm = wid >> 1;         // 0..1 -> m offset *64
    const int wn = wid & 1;          // 0..1 -> n offset *64

    const int z = blockIdx.z;
    const int n0 = blockIdx.x * GBN;
    const int m0 = blockIdx.y * GBM;
    const __nv_bfloat16* __restrict__ whi = g_whi + (size_t)z * HID * OBS;
    const __nv_bfloat16* __restrict__ wlo = g_wlo + (size_t)z * HID * OBS;

    float acc[4][8][4];   // [mi][n8-frag][frag]
#pragma unroll
    for (int i = 0; i < 4; i++)
#pragma unroll
        for (int j = 0; j < 8; j++)
#pragma unroll
            for (int k = 0; k < 4; k++) acc[i][j][k] = 0.f;

    auto load_stage = [&](int s, int bi) {
        const int k0 = s * GBK;
        const uint32_t st = sbase + bi * STAGE_BYTES;
#pragma unroll
        for (int i = 0; i < 4; i++) {
            int idx = tid + 128 * i;          // 0..511
            int row = idx >> 2, c = idx & 3;
            size_t gsrc = (size_t)(m0 + row) * OBS + k0 + c * 8;
            uint32_t dst = st + row * ROWB + c * 16;
            cp16(dst,           g_xhi + gsrc);
            cp16(dst + A_BYTES, g_xlo + gsrc);
        }
#pragma unroll
        for (int i = 0; i < 4; i++) {
            int idx = tid + 128 * i;
            int row = idx >> 2, c = idx & 3;
            size_t gsrc = (size_t)(n0 + row) * OBS + k0 + c * 8;
            uint32_t dst = st + 2 * A_BYTES + row * ROWB + c * 16;
            cp16(dst,           whi + gsrc);
            cp16(dst + B_BYTES, wlo + gsrc);
        }
        cp_commit();
    };

    load_stage(0, 0);

    for (int s = 0; s < NS; s++) {
        if (s + 1 < NS) {
            load_stage(s + 1, (s + 1) & 1);
            asm volatile("cp.async.wait_group 1;" ::: "memory");
        } else {
            asm volatile("cp.async.wait_group 0;" ::: "memory");
        }
        __syncthreads();

        const uint32_t ab = sbase + (s & 1) * STAGE_BYTES;   // A hi
        const uint32_t bb = ab + 2 * A_BYTES;                // B hi

#pragma unroll
        for (int ks = 0; ks < 2; ks++) {
            uint32_t ahi[4][4], alo[4][4];
#pragma unroll
            for (int mi = 0; mi < 4; mi++) {
                uint32_t addr = ab + (wm * 64 + mi * 16 + (lane & 15)) * ROWB
                              + ks * 32 + (lane >> 4) * 16;
                ldsm4(ahi[mi], addr);
                ldsm4(alo[mi], addr + A_BYTES);
            }
            uint32_t bhi[4][4], blo[4][4];
#pragma unroll
            for (int np = 0; np < 4; np++) {
                uint32_t addr = bb + (wn * 64 + np * 16 + (lane >> 4) * 8 + (lane & 7)) * ROWB
                              + ks * 32 + ((lane >> 3) & 1) * 16;
                ldsm4(bhi[np], addr);
                ldsm4(blo[np], addr + B_BYTES);
            }
#pragma unroll
            for (int mi = 0; mi < 4; mi++)
#pragma unroll
                for (int np = 0; np < 4; np++) {
                    mma16816(acc[mi][np * 2],     ahi[mi], bhi[np][0], bhi[np][1]);
                    mma16816(acc[mi][np * 2 + 1], ahi[mi], bhi[np][2], bhi[np][3]);
                }
#pragma unroll
            for (int mi = 0; mi < 4; mi++)
#pragma unroll
                for (int np = 0; np < 4; np++) {
                    mma16816(acc[mi][np * 2],     ahi[mi], blo[np][0], blo[np][1]);
                    mma16816(acc[mi][np * 2 + 1], ahi[mi], blo[np][2], blo[np][3]);
                }
#pragma unroll
            for (int mi = 0; mi < 4; mi++)
#pragma unroll
                for (int np = 0; np < 4; np++) {
                    mma16816(acc[mi][np * 2],     alo[mi], bhi[np][0], bhi[np][1]);
                    mma16816(acc[mi][np * 2 + 1], alo[mi], bhi[np][2], bhi[np][3]);
                }
        }
        __syncthreads();
    }

    // Epilogue: z<3 -> fp16; z==3 (delta_raw) -> fp32
    if (z == 3) {
        float* __restrict__ G = g_buf[3];
#pragma unroll
        for (int mi = 0; mi < 4; mi++) {
            int row = m0 + wm * 64 + mi * 16 + (lane >> 2);
#pragma unroll
            for (int ni = 0; ni < 8; ni++) {
                int col = n0 + wn * 64 + ni * 8 + (lane & 3) * 2;
                *(float2*)(G + (size_t)row * HID + col) =
                    make_float2(acc[mi][ni][0], acc[mi][ni][1]);
                *(float2*)(G + (size_t)(row + 8) * HID + col) =
                    make_float2(acc[mi][ni][2], acc[mi][ni][3]);
            }
        }
    } else {
        __half* __restrict__ H = g_h16[z];
#pragma unroll
        for (int mi = 0; mi < 4; mi++) {
            int row = m0 + wm * 64 + mi * 16 + (lane >> 2);
#pragma unroll
            for (int ni = 0; ni < 8; ni++) {
                int col = n0 + wn * 64 + ni * 8 + (lane & 3) * 2;
                *(__half2*)(H + (size_t)row * HID + col) =
                    __floats2half2_rn(acc[mi][ni][0], acc[mi][ni][1]);
                *(__half2*)(H + (size_t)(row + 8) * HID + col) =
                    __floats2half2_rn(acc[mi][ni][2], acc[mi][ni][3]);
            }
        }
    }
}

// ---------------------------------------------------------------------------
// Scan pass 1: per-chunk aggregates only (scalar, 1024 blocks — proven config).
// ---------------------------------------------------------------------------
__global__ void scan_chunk_kernel(const float* __restrict__ A_log) {
    int h = blockIdx.x * blockDim.x + threadIdx.x;
    int c = blockIdx.y;
    float A = -expf(A_log[h]);
    size_t base = (size_t)(c * LC) * HID + h;
    float ap = 1.f, bb = 0.f;
#pragma unroll 4
    for (int i = 0; i < LC; i++) {
        float dr = g_buf[3][base];
        float xs = __half2float(g_h16[0][base]);
        float Bv = __half2float(g_h16[1][base]);
        float delta = 1.f / (1.f + __expf(-dr));
        float a = expf(delta * A);
        float bx = Bv * xs;
        ap *= a;
        bb = a * bb + bx;
        base += HID;
    }
    g_aggA[c * HID + h] = ap;
    g_aggB[c * HID + h] = bb;
}

// ---------------------------------------------------------------------------
// Scan pass 2: warp-parallel scan of NCHUNK aggregates per channel.
// ---------------------------------------------------------------------------
__global__ void scan_agg_kernel() {
    int warp = threadIdx.x >> 5;
    int lane = threadIdx.x & 31;
    int h = blockIdx.x * 8 + warp;

    float a_loc[4], b_loc[4];
    float ca = 1.f, cb = 0.f;
    int cbase = lane * 4;
#pragma unroll
    for (int j = 0; j < 4; j++) {
        float a = g_aggA[(cbase + j) * HID + h];
        float b = g_aggB[(cbase + j) * HID + h];
        a_loc[j] = a; b_loc[j] = b;
        cb = a * cb + b;
        ca *= a;
    }
    float ia = ca, ib = cb;
#pragma unroll
    for (int off = 1; off < 32; off <<= 1) {
        float pa = __shfl_up_sync(0xFFFFFFFFu, ia, off);
        float pb = __shfl_up_sync(0xFFFFFFFFu, ib, off);
        if (lane >= off) {
            ib = ia * pb + ib;
            ia = ia * pa;
        }
    }
    float eb = __shfl_up_sync(0xFFFFFFFFu, ib, 1);
    if (lane == 0) eb = 0.f;
    float hcur = eb;
#pragma unroll
    for (int j = 0; j < 4; j++) {
        g_hinit[(cbase + j) * HID + h] = hcur;
        hcur = a_loc[j] * hcur + b_loc[j];
    }
}

// ---------------------------------------------------------------------------
// Scan pass 3: apply within chunk (scalar); y = C*h stored as fp16.
// ---------------------------------------------------------------------------
__global__ void scan_apply_kernel(const float* __restrict__ A_log) {
    int h = blockIdx.x * blockDim.x + threadIdx.x;
    int c = blockIdx.y;
    float A = -expf(A_log[h]);
    size_t base = (size_t)(c * LC) * HID + h;
    float hs = g_hinit[c * HID + h];
#pragma unroll 4
    for (int i = 0; i < LC; i++) {
        float dr = g_buf[3][base];
        float xs = __half2float(g_h16[0][base]);
        float Bv = __half2float(g_h16[1][base]);
        float Cv = __half2float(g_h16[2][base]);
        float delta = 1.f / (1.f + __expf(-dr));
        float a = expf(delta * A);
        hs = a * hs + Bv * xs;
        g_y16[base] = __float2half_rn(Cv * hs);
        base += HID;
    }
}

// ---------------------------------------------------------------------------
// Output projection: warp per timestep; y read as fp16.
// ---------------------------------------------------------------------------
__global__ void out_kernel(const float* __restrict__ x,
                           const float* __restrict__ W_out,
                           const float* __restrict__ b_out,
                           const float* __restrict__ W_skip,
                           float* __restrict__ out) {
    int warp = threadIdx.x >> 5;
    int lane = threadIdx.x & 31;
    int t = blockIdx.x * (blockDim.x >> 5) + warp;
    if (t >= T_DIM) return;

    float acc[NOBJ];
#pragma unroll
    for (int n = 0; n < NOBJ; n++) acc[n] = 0.f;

    const __half* yrow = g_y16 + (size_t)t * HID;
    for (int h = lane; h < HID; h += 32) {
        float yv = __half2float(yrow[h]);
#pragma unroll
        for (int n = 0; n < NOBJ; n++) acc[n] += yv * W_out[n * HID + h];
    }
    const float* xrow = x + (size_t)t * OBS;
    for (int o = lane; o < OBS; o += 32) {
        float xv = xrow[o];
#pragma unroll
        for (int n = 0; n < NOBJ; n++) acc[n] += xv * W_skip[n * OBS + o];
    }
#pragma unroll
    for (int n = 0; n < NOBJ; n++) {
#pragma unroll
        for (int off = 16; off > 0; off >>= 1)
            acc[n] += __shfl_down_sync(0xFFFFFFFFu, acc[n], off);
    }
    if (lane == 0) {
#pragma unroll
        for (int n = 0; n < NOBJ; n++)
            out[(size_t)t * NOBJ + n] = acc[n] + b_out[n];
    }
}

// ---------------------------------------------------------------------------
extern "C" void kernel_launch(void* const* d_in, const int* in_sizes, int n_in,
                              void* d_out, int out_size) {
    const float* x       = (const float*)d_in[0];
    const float* W_in    = (const float*)d_in[1];
    const float* W_B     = (const float*)d_in[2];
    const float* W_C     = (const float*)d_in[3];
    const float* W_delta = (const float*)d_in[4];
    const float* A_log   = (const float*)d_in[5];
    const float* W_out   = (const float*)d_in[6];
    const float* b_out   = (const float*)d_in[7];
    const float* W_skip  = (const float*)d_in[8];
    float* out = (float*)d_out;

    cudaFuncSetAttribute(gemm_hmma_kernel, cudaFuncAttributeMaxDynamicSharedMemorySize, GEMM_SMEM);

    // 0) bf16 hi/lo split of X and the four weight matrices
    convert_x_kernel<<<(T_DIM * OBS) / 1024, 256>>>(x);
    convert_w_kernel<<<dim3((HID * OBS) / 1024, 4), 256>>>(W_in, W_B, W_C, W_delta);

    // 1) 4 GEMMs on tensor cores; fp16 outputs for x_state/B/C, fp32 delta_raw
    gemm_hmma_kernel<<<dim3(HID / GBN, T_DIM / GBM, 4), 128, GEMM_SMEM>>>();

    // 2+3) chunked scan (scalar, 1024-block config — proven)
    scan_chunk_kernel<<<dim3(HID / 256, NCHUNK), 256>>>(A_log);
    scan_agg_kernel<<<HID / 8, 256>>>();
    scan_apply_kernel<<<dim3(HID / 256, NCHUNK), 256>>>(A_log);

    // 4) output projection
    out_kernel<<<T_DIM / 8, 256>>>(x, W_out, b_out, W_skip, out);
}

// round 17
// speedup vs baseline: 1.5020x; 1.0029x over previous
#include <cuda_runtime.h>
#include <cuda_bf16.h>
#include <cuda_fp16.h>
#include <math.h>
#include <stdint.h>

#define T_DIM 8192
#define OBS 512
#define HID 2048
#define NOBJ 8

#define NCHUNK 128
#define LC (T_DIM / NCHUNK)   // 64

// ---------------------------------------------------------------------------
// Scratch (device globals; no allocation allowed).
// g_h16[0]=x_state, g_h16[1]=B, g_h16[2]=C, g_h16[3]=delta_raw (all fp16);
// g_y16 = y (fp16, scan output)
__device__ __half g_h16[4][(size_t)T_DIM * HID];
__device__ __half g_y16[(size_t)T_DIM * HID];
__device__ float g_aggA[NCHUNK * HID];
__device__ float g_aggB[NCHUNK * HID];
__device__ float g_hinit[NCHUNK * HID];
// bf16 hi/lo split operands
__device__ __nv_bfloat16 g_xhi[(size_t)T_DIM * OBS];
__device__ __nv_bfloat16 g_xlo[(size_t)T_DIM * OBS];
__device__ __nv_bfloat16 g_whi[4ull * HID * OBS];
__device__ __nv_bfloat16 g_wlo[4ull * HID * OBS];

// ---------------------------------------------------------------------------
__device__ __forceinline__ uint32_t smem_to_u32(const void* p) {
    uint32_t a;
    asm("{ .reg .u64 t; cvta.to.shared.u64 t, %1; cvt.u32.u64 %0, t; }" : "=r"(a) : "l"(p));
    return a;
}
__device__ __forceinline__ void cp16(uint32_t dst, const void* src) {
    asm volatile("cp.async.cg.shared.global [%0], [%1], 16;" :: "r"(dst), "l"(src));
}
__device__ __forceinline__ void cp_commit() { asm volatile("cp.async.commit_group;"); }
__device__ __forceinline__ void ldsm4(uint32_t* r, uint32_t addr) {
    asm volatile("ldmatrix.sync.aligned.m8n8.x4.shared.b16 {%0,%1,%2,%3}, [%4];"
                 : "=r"(r[0]), "=r"(r[1]), "=r"(r[2]), "=r"(r[3]) : "r"(addr));
}
__device__ __forceinline__ void mma16816(float* c, const uint32_t* a, uint32_t b0, uint32_t b1) {
    asm volatile(
        "mma.sync.aligned.m16n8k16.row.col.f32.bf16.bf16.f32 "
        "{%0,%1,%2,%3}, {%4,%5,%6,%7}, {%8,%9}, {%0,%1,%2,%3};"
        : "+f"(c[0]), "+f"(c[1]), "+f"(c[2]), "+f"(c[3])
        : "r"(a[0]), "r"(a[1]), "r"(a[2]), "r"(a[3]), "r"(b0), "r"(b1));
}
__device__ __forceinline__ uint32_t pack_bf16x2(float a, float b) {
    __nv_bfloat162 p = __floats2bfloat162_rn(a, b);
    return *(uint32_t*)&p;
}

// ---------------------------------------------------------------------------
// fp32 -> bf16 hi/lo conversion (vectorized)
// ---------------------------------------------------------------------------
__global__ void convert_x_kernel(const float* __restrict__ x) {
    size_t i = ((size_t)blockIdx.x * blockDim.x + threadIdx.x) * 4;
    float4 v = *(const float4*)(x + i);
    __nv_bfloat16 h0 = __float2bfloat16(v.x), h1 = __float2bfloat16(v.y);
    __nv_bfloat16 h2 = __float2bfloat16(v.z), h3 = __float2bfloat16(v.w);
    uint2 hp;
    hp.x = pack_bf16x2(__bfloat162float(h0), __bfloat162float(h1));
    hp.y = pack_bf16x2(__bfloat162float(h2), __bfloat162float(h3));
    *(uint2*)(g_xhi + i) = hp;
    uint2 lp;
    lp.x = pack_bf16x2(v.x - __bfloat162float(h0), v.y - __bfloat162float(h1));
    lp.y = pack_bf16x2(v.z - __bfloat162float(h2), v.w - __bfloat162float(h3));
    *(uint2*)(g_xlo + i) = lp;
}
__global__ void convert_w_kernel(const float* __restrict__ w0, const float* __restrict__ w1,
                                 const float* __restrict__ w2, const float* __restrict__ w3) {
    int z = blockIdx.y;
    const float* __restrict__ W = (z == 0) ? w0 : (z == 1) ? w1 : (z == 2) ? w2 : w3;
    size_t i = ((size_t)blockIdx.x * blockDim.x + threadIdx.x) * 4;
    float4 v = *(const float4*)(W + i);
    size_t o = (size_t)z * HID * OBS + i;
    __nv_bfloat16 h0 = __float2bfloat16(v.x), h1 = __float2bfloat16(v.y);
    __nv_bfloat16 h2 = __float2bfloat16(v.z), h3 = __float2bfloat16(v.w);
    uint2 hp;
    hp.x = pack_bf16x2(__bfloat162float(h0), __bfloat162float(h1));
    hp.y = pack_bf16x2(__bfloat162float(h2), __bfloat162float(h3));
    *(uint2*)(g_whi + o) = hp;
    uint2 lp;
    lp.x = pack_bf16x2(v.x - __bfloat162float(h0), v.y - __bfloat162float(h1));
    lp.y = pack_bf16x2(v.z - __bfloat162float(h2), v.w - __bfloat162float(h3));
    *(uint2*)(g_wlo + o) = lp;
}

// ---------------------------------------------------------------------------
// HMMA GEMM (proven ~122us/GEMM): G[z] = X . W_z^T, bf16 3-term hi/lo.
// BM=128, BN=128, BK=32. 4 warps 2x2, warp tile 64x64. 128 thr, 2 CTAs/SM.
// Epilogue: all four z stored as fp16 (delta_raw fp16 is precision-safe:
// it perturbs the decay exponent multiplicatively, see round analysis).
// ---------------------------------------------------------------------------
#define GBM 128
#define GBN 128
#define GBK 32
#define NS (OBS / GBK)           // 16
#define ROWB 80
#define A_BYTES (GBM * ROWB)     // 10240
#define B_BYTES (GBN * ROWB)     // 10240
#define STAGE_BYTES (2 * A_BYTES + 2 * B_BYTES)   // 40960
#define GEMM_SMEM (2 * STAGE_BYTES)               // 81920

__global__ __launch_bounds__(128, 2)
void gemm_hmma_kernel() {
    extern __shared__ char smem[];
    const uint32_t sbase = smem_to_u32(smem);
    const int tid = threadIdx.x;
    const int wid = tid >> 5;
    const int lane = tid & 31;
    const int wm = wid >> 1;         // 0..1 -> m offset *64
    const int wn = wid & 1;          // 0..1 -> n offset *64

    const int z = blockIdx.z;
    const int n0 = blockIdx.x * GBN;
    const int m0 = blockIdx.y * GBM;
    const __nv_bfloat16* __restrict__ whi = g_whi + (size_t)z * HID * OBS;
    const __nv_bfloat16* __restrict__ wlo = g_wlo + (size_t)z * HID * OBS;

    float acc[4][8][4];   // [mi][n8-frag][frag]
#pragma unroll
    for (int i = 0; i < 4; i++)
#pragma unroll
        for (int j = 0; j < 8; j++)
#pragma unroll
            for (int k = 0; k < 4; k++) acc[i][j][k] = 0.f;

    auto load_stage = [&](int s, int bi) {
        const int k0 = s * GBK;
        const uint32_t st = sbase + bi * STAGE_BYTES;
#pragma unroll
        for (int i = 0; i < 4; i++) {
            int idx = tid + 128 * i;          // 0..511
            int row = idx >> 2, c = idx & 3;
            size_t gsrc = (size_t)(m0 + row) * OBS + k0 + c * 8;
            uint32_t dst = st + row * ROWB + c * 16;
            cp16(dst,           g_xhi + gsrc);
            cp16(dst + A_BYTES, g_xlo + gsrc);
        }
#pragma unroll
        for (int i = 0; i < 4; i++) {
            int idx = tid + 128 * i;
            int row = idx >> 2, c = idx & 3;
            size_t gsrc = (size_t)(n0 + row) * OBS + k0 + c * 8;
            uint32_t dst = st + 2 * A_BYTES + row * ROWB + c * 16;
            cp16(dst,           whi + gsrc);
            cp16(dst + B_BYTES, wlo + gsrc);
        }
        cp_commit();
    };

    load_stage(0, 0);

    for (int s = 0; s < NS; s++) {
        if (s + 1 < NS) {
            load_stage(s + 1, (s + 1) & 1);
            asm volatile("cp.async.wait_group 1;" ::: "memory");
        } else {
            asm volatile("cp.async.wait_group 0;" ::: "memory");
        }
        __syncthreads();

        const uint32_t ab = sbase + (s & 1) * STAGE_BYTES;   // A hi
        const uint32_t bb = ab + 2 * A_BYTES;                // B hi

#pragma unroll
        for (int ks = 0; ks < 2; ks++) {
            uint32_t ahi[4][4], alo[4][4];
#pragma unroll
            for (int mi = 0; mi < 4; mi++) {
                uint32_t addr = ab + (wm * 64 + mi * 16 + (lane & 15)) * ROWB
                              + ks * 32 + (lane >> 4) * 16;
                ldsm4(ahi[mi], addr);
                ldsm4(alo[mi], addr + A_BYTES);
            }
            uint32_t bhi[4][4], blo[4][4];
#pragma unroll
            for (int np = 0; np < 4; np++) {
                uint32_t addr = bb + (wn * 64 + np * 16 + (lane >> 4) * 8 + (lane & 7)) * ROWB
                              + ks * 32 + ((lane >> 3) & 1) * 16;
                ldsm4(bhi[np], addr);
                ldsm4(blo[np], addr + B_BYTES);
            }
#pragma unroll
            for (int mi = 0; mi < 4; mi++)
#pragma unroll
                for (int np = 0; np < 4; np++) {
                    mma16816(acc[mi][np * 2],     ahi[mi], bhi[np][0], bhi[np][1]);
                    mma16816(acc[mi][np * 2 + 1], ahi[mi], bhi[np][2], bhi[np][3]);
                }
#pragma unroll
            for (int mi = 0; mi < 4; mi++)
#pragma unroll
                for (int np = 0; np < 4; np++) {
                    mma16816(acc[mi][np * 2],     ahi[mi], blo[np][0], blo[np][1]);
                    mma16816(acc[mi][np * 2 + 1], ahi[mi], blo[np][2], blo[np][3]);
                }
#pragma unroll
            for (int mi = 0; mi < 4; mi++)
#pragma unroll
                for (int np = 0; np < 4; np++) {
                    mma16816(acc[mi][np * 2],     alo[mi], bhi[np][0], bhi[np][1]);
                    mma16816(acc[mi][np * 2 + 1], alo[mi], bhi[np][2], bhi[np][3]);
                }
        }
        __syncthreads();
    }

    // Epilogue: all planes fp16
    __half* __restrict__ H = g_h16[z];
#pragma unroll
    for (int mi = 0; mi < 4; mi++) {
        int row = m0 + wm * 64 + mi * 16 + (lane >> 2);
#pragma unroll
        for (int ni = 0; ni < 8; ni++) {
            int col = n0 + wn * 64 + ni * 8 + (lane & 3) * 2;
            *(__half2*)(H + (size_t)row * HID + col) =
                __floats2half2_rn(acc[mi][ni][0], acc[mi][ni][1]);
            *(__half2*)(H + (size_t)(row + 8) * HID + col) =
                __floats2half2_rn(acc[mi][ni][2], acc[mi][ni][3]);
        }
    }
}

// ---------------------------------------------------------------------------
// Scan pass 1: per-chunk aggregates only (scalar, 1024 blocks — proven config).
// ---------------------------------------------------------------------------
__global__ void scan_chunk_kernel(const float* __restrict__ A_log) {
    int h = blockIdx.x * blockDim.x + threadIdx.x;
    int c = blockIdx.y;
    float A = -expf(A_log[h]);
    size_t base = (size_t)(c * LC) * HID + h;
    float ap = 1.f, bb = 0.f;
#pragma unroll 4
    for (int i = 0; i < LC; i++) {
        float dr = __half2float(g_h16[3][base]);
        float xs = __half2float(g_h16[0][base]);
        float Bv = __half2float(g_h16[1][base]);
        float delta = 1.f / (1.f + __expf(-dr));
        float a = expf(delta * A);
        float bx = Bv * xs;
        ap *= a;
        bb = a * bb + bx;
        base += HID;
    }
    g_aggA[c * HID + h] = ap;
    g_aggB[c * HID + h] = bb;
}

// ---------------------------------------------------------------------------
// Scan pass 2: warp-parallel scan of NCHUNK aggregates per channel.
// ---------------------------------------------------------------------------
__global__ void scan_agg_kernel() {
    int warp = threadIdx.x >> 5;
    int lane = threadIdx.x & 31;
    int h = blockIdx.x * 8 + warp;

    float a_loc[4], b_loc[4];
    float ca = 1.f, cb = 0.f;
    int cbase = lane * 4;
#pragma unroll
    for (int j = 0; j < 4; j++) {
        float a = g_aggA[(cbase + j) * HID + h];
        float b = g_aggB[(cbase + j) * HID + h];
        a_loc[j] = a; b_loc[j] = b;
        cb = a * cb + b;
        ca *= a;
    }
    float ia = ca, ib = cb;
#pragma unroll
    for (int off = 1; off < 32; off <<= 1) {
        float pa = __shfl_up_sync(0xFFFFFFFFu, ia, off);
        float pb = __shfl_up_sync(0xFFFFFFFFu, ib, off);
        if (lane >= off) {
            ib = ia * pb + ib;
            ia = ia * pa;
        }
    }
    float eb = __shfl_up_sync(0xFFFFFFFFu, ib, 1);
    if (lane == 0) eb = 0.f;
    float hcur = eb;
#pragma unroll
    for (int j = 0; j < 4; j++) {
        g_hinit[(cbase + j) * HID + h] = hcur;
        hcur = a_loc[j] * hcur + b_loc[j];
    }
}

// ---------------------------------------------------------------------------
// Scan pass 3: apply within chunk (scalar); y = C*h stored as fp16.
// ---------------------------------------------------------------------------
__global__ void scan_apply_kernel(const float* __restrict__ A_log) {
    int h = blockIdx.x * blockDim.x + threadIdx.x;
    int c = blockIdx.y;
    float A = -expf(A_log[h]);
    size_t base = (size_t)(c * LC) * HID + h;
    float hs = g_hinit[c * HID + h];
#pragma unroll 4
    for (int i = 0; i < LC; i++) {
        float dr = __half2float(g_h16[3][base]);
        float xs = __half2float(g_h16[0][base]);
        float Bv = __half2float(g_h16[1][base]);
        float Cv = __half2float(g_h16[2][base]);
        float delta = 1.f / (1.f + __expf(-dr));
        float a = expf(delta * A);
        hs = a * hs + Bv * xs;
        g_y16[base] = __float2half_rn(Cv * hs);
        base += HID;
    }
}

// ---------------------------------------------------------------------------
// Output projection: warp per timestep; y read as fp16.
// ---------------------------------------------------------------------------
__global__ void out_kernel(const float* __restrict__ x,
                           const float* __restrict__ W_out,
                           const float* __restrict__ b_out,
                           const float* __restrict__ W_skip,
                           float* __restrict__ out) {
    int warp = threadIdx.x >> 5;
    int lane = threadIdx.x & 31;
    int t = blockIdx.x * (blockDim.x >> 5) + warp;
    if (t >= T_DIM) return;

    float acc[NOBJ];
#pragma unroll
    for (int n = 0; n < NOBJ; n++) acc[n] = 0.f;

    const __half* yrow = g_y16 + (size_t)t * HID;
    for (int h = lane; h < HID; h += 32) {
        float yv = __half2float(yrow[h]);
#pragma unroll
        for (int n = 0; n < NOBJ; n++) acc[n] += yv * W_out[n * HID + h];
    }
    const float* xrow = x + (size_t)t * OBS;
    for (int o = lane; o < OBS; o += 32) {
        float xv = xrow[o];
#pragma unroll
        for (int n = 0; n < NOBJ; n++) acc[n] += xv * W_skip[n * OBS + o];
    }
#pragma unroll
    for (int n = 0; n < NOBJ; n++) {
#pragma unroll
        for (int off = 16; off > 0; off >>= 1)
            acc[n] += __shfl_down_sync(0xFFFFFFFFu, acc[n], off);
    }
    if (lane == 0) {
#pragma unroll
        for (int n = 0; n < NOBJ; n++)
            out[(size_t)t * NOBJ + n] = acc[n] + b_out[n];
    }
}

// ---------------------------------------------------------------------------
extern "C" void kernel_launch(void* const* d_in, const int* in_sizes, int n_in,
                              void* d_out, int out_size) {
    const float* x       = (const float*)d_in[0];
    const float* W_in    = (const float*)d_in[1];
    const float* W_B     = (const float*)d_in[2];
    const float* W_C     = (const float*)d_in[3];
    const float* W_delta = (const float*)d_in[4];
    const float* A_log   = (const float*)d_in[5];
    const float* W_out   = (const float*)d_in[6];
    const float* b_out   = (const float*)d_in[7];
    const float* W_skip  = (const float*)d_in[8];
    float* out = (float*)d_out;

    cudaFuncSetAttribute(gemm_hmma_kernel, cudaFuncAttributeMaxDynamicSharedMemorySize, GEMM_SMEM);

    // 0) bf16 hi/lo split of X and the four weight matrices
    convert_x_kernel<<<(T_DIM * OBS) / 1024, 256>>>(x);
    convert_w_kernel<<<dim3((HID * OBS) / 1024, 4), 256>>>(W_in, W_B, W_C, W_delta);

    // 1) 4 GEMMs on tensor cores; all intermediates fp16
    gemm_hmma_kernel<<<dim3(HID / GBN, T_DIM / GBM, 4), 128, GEMM_SMEM>>>();

    // 2+3) chunked scan (scalar, 1024-block config — proven)
    scan_chunk_kernel<<<dim3(HID / 256, NCHUNK), 256>>>(A_log);
    scan_agg_kernel<<<HID / 8, 256>>>();
    scan_apply_kernel<<<dim3(HID / 256, NCHUNK), 256>>>(A_log);

    // 4) output projection
    out_kernel<<<T_DIM / 8, 256>>>(x, W_out, b_out, W_skip, out);
}